// round 5
// baseline (speedup 1.0000x reference)
#include <cuda_runtime.h>

#define NB 2048
#define NF 64
#define NR 32
#define NP 16
#define NC 128

// ---------------- scratch ----------------
__device__ float g_wch [NB*1024];
__device__ float g_vch [NB*1024];
__device__ float g_vep0[NB*1024];
__device__ float g_vep2[NB*1024];
__device__ float g_Wk  [3*NB*1024];
__device__ float g_small[NB*264];     // 258 small projections per batch (padded)

__device__ __forceinline__ float sigmoidf_(float x) { return 1.f/(1.f + __expf(-x)); }

// =====================================================================
// Kernel 1: 7 uniform GEMMs (2048 x 1024 x 128), z selects projection.
// =====================================================================
__global__ __launch_bounds__(256) void proj_gemm(
    const float* __restrict__ ctx,
    const float* __restrict__ wch_W, const float* __restrict__ wch_b,
    const float* __restrict__ vch_W, const float* __restrict__ vch_b,
    const float* __restrict__ vep_W, const float* __restrict__ vep_b,
    const float* __restrict__ m_W,   const float* __restrict__ m_Wb)
{
    const float* W; const float* bias; float* outp;
    int nstride = 1, noff = 0, ldw = 1024;
    switch (blockIdx.z) {
        case 0: W = wch_W; bias = wch_b; outp = g_wch; break;
        case 1: W = vch_W; bias = vch_b; outp = g_vch; break;
        case 2: W = vep_W; bias = vep_b; outp = g_vep0; ldw = 4096; nstride = 4; noff = 0; break;
        case 3: W = vep_W; bias = vep_b; outp = g_vep2; ldw = 4096; nstride = 4; noff = 2; break;
        default: { int k = blockIdx.z - 4;
                   W = m_W + k*NC*1024; bias = m_Wb + k*1024; outp = g_Wk + k*NB*1024; } break;
    }
    const int n0 = blockIdx.x * 64;
    const int m0 = blockIdx.y * 64;

    __shared__ float As[64][65];
    __shared__ __align__(16) float Bs[64][64];

    const int t  = threadIdx.x;
    const int tx = t & 15, ty = t >> 4;

    float acc[4][4];
    #pragma unroll
    for (int i = 0; i < 4; i++)
        #pragma unroll
        for (int j = 0; j < 4; j++) acc[i][j] = 0.f;

    for (int k0 = 0; k0 < 128; k0 += 64) {
        #pragma unroll 4
        for (int i = t; i < 64*64; i += 256) {
            int m = i >> 6, k = i & 63;
            As[k][m] = ctx[(m0+m)*NC + k0 + k];
        }
        #pragma unroll 4
        for (int i = t; i < 64*64; i += 256) {
            int k = i >> 6, n = i & 63;
            Bs[k][n] = W[(k0+k)*ldw + (n0+n)*nstride + noff];
        }
        __syncthreads();
        #pragma unroll 16
        for (int k = 0; k < 64; k++) {
            float a0 = As[k][ty*4+0], a1 = As[k][ty*4+1];
            float a2 = As[k][ty*4+2], a3 = As[k][ty*4+3];
            float4 bv = *(const float4*)&Bs[k][tx*4];
            acc[0][0] += a0*bv.x; acc[0][1] += a0*bv.y; acc[0][2] += a0*bv.z; acc[0][3] += a0*bv.w;
            acc[1][0] += a1*bv.x; acc[1][1] += a1*bv.y; acc[1][2] += a1*bv.z; acc[1][3] += a1*bv.w;
            acc[2][0] += a2*bv.x; acc[2][1] += a2*bv.y; acc[2][2] += a2*bv.z; acc[2][3] += a2*bv.w;
            acc[3][0] += a3*bv.x; acc[3][1] += a3*bv.y; acc[3][2] += a3*bv.z; acc[3][3] += a3*bv.w;
        }
        __syncthreads();
    }

    float b0 = bias[(n0+tx*4+0)*nstride + noff];
    float b1 = bias[(n0+tx*4+1)*nstride + noff];
    float b2 = bias[(n0+tx*4+2)*nstride + noff];
    float b3 = bias[(n0+tx*4+3)*nstride + noff];
    #pragma unroll
    for (int i = 0; i < 4; i++) {
        int m = m0 + ty*4 + i;
        float4 o;
        o.x = acc[i][0] + b0; o.y = acc[i][1] + b1;
        o.z = acc[i][2] + b2; o.w = acc[i][3] + b3;
        *(float4*)&outp[m*1024 + n0 + tx*4] = o;
    }
}

// =====================================================================
// Kernel 1b: all 258 small projections as one gather-GEMM (2048x258x128).
// Column map: [0,96)=mod, [96,112)=wdl, [112,128)=wep ch0, [128,144)=wep ch2,
//             [144,208)=wnc, [208,256)=mb (k=idx>>4,p=idx&15), 256=wnd, 257=wne.
// =====================================================================
__device__ __forceinline__ const float* sp_col(int n, int& stride,
    const float* mod_W, const float* wdl_W, const float* wep_W,
    const float* wnc_W, const float* mb_W, const float* wnd_W, const float* wne_W)
{
    if (n < 96)  { stride = 96; return mod_W + n; }
    if (n < 112) { stride = 16; return wdl_W + (n-96); }
    if (n < 128) { stride = 64; return wep_W + (n-112)*4; }
    if (n < 144) { stride = 64; return wep_W + (n-128)*4 + 2; }
    if (n < 208) { stride = 64; return wnc_W + (n-144); }
    if (n < 256) { int idx = n-208; stride = 16; return mb_W + (idx>>4)*2048 + (idx&15); }
    if (n == 256){ stride = 1; return wnd_W; }
    stride = 1; return wne_W;
}
__device__ __forceinline__ float sp_bias(int n,
    const float* mod_b, const float* wdl_b, const float* wep_b,
    const float* wnc_b, const float* mb_b, const float* wnd_b, const float* wne_b)
{
    if (n < 96)  return mod_b[n];
    if (n < 112) return wdl_b[n-96];
    if (n < 128) return wep_b[(n-112)*4];
    if (n < 144) return wep_b[(n-128)*4 + 2];
    if (n < 208) return wnc_b[n-144];
    if (n < 256) return mb_b[n-208];
    if (n == 256) return wnd_b[0];
    return wne_b[0];
}

__global__ __launch_bounds__(256) void small_proj(
    const float* __restrict__ ctx,
    const float* __restrict__ mod_W, const float* __restrict__ mod_b,
    const float* __restrict__ wdl_W, const float* __restrict__ wdl_b,
    const float* __restrict__ wep_W, const float* __restrict__ wep_b,
    const float* __restrict__ wnc_W, const float* __restrict__ wnc_b,
    const float* __restrict__ mb_W,  const float* __restrict__ mb_b,
    const float* __restrict__ wnd_W, const float* __restrict__ wnd_b,
    const float* __restrict__ wne_W, const float* __restrict__ wne_b)
{
    const int n0 = blockIdx.x * 64;
    const int m0 = blockIdx.y * 64;

    __shared__ float As[64][65];
    __shared__ __align__(16) float Bs[64][64];

    const int t  = threadIdx.x;
    const int tx = t & 15, ty = t >> 4;

    float acc[4][4];
    #pragma unroll
    for (int i = 0; i < 4; i++)
        #pragma unroll
        for (int j = 0; j < 4; j++) acc[i][j] = 0.f;

    for (int k0 = 0; k0 < 128; k0 += 64) {
        #pragma unroll 4
        for (int i = t; i < 64*64; i += 256) {
            int m = i >> 6, k = i & 63;
            As[k][m] = ctx[(m0+m)*NC + k0 + k];
        }
        #pragma unroll 4
        for (int i = t; i < 64*64; i += 256) {
            int k = i >> 6, nl = i & 63;
            int n = n0 + nl;
            float v = 0.f;
            if (n < 258) {
                int stride; const float* p = sp_col(n, stride, mod_W, wdl_W, wep_W, wnc_W, mb_W, wnd_W, wne_W);
                v = p[(k0+k)*stride];
            }
            Bs[k][nl] = v;
        }
        __syncthreads();
        #pragma unroll 16
        for (int k = 0; k < 64; k++) {
            float a0 = As[k][ty*4+0], a1 = As[k][ty*4+1];
            float a2 = As[k][ty*4+2], a3 = As[k][ty*4+3];
            float4 bv = *(const float4*)&Bs[k][tx*4];
            acc[0][0] += a0*bv.x; acc[0][1] += a0*bv.y; acc[0][2] += a0*bv.z; acc[0][3] += a0*bv.w;
            acc[1][0] += a1*bv.x; acc[1][1] += a1*bv.y; acc[1][2] += a1*bv.z; acc[1][3] += a1*bv.w;
            acc[2][0] += a2*bv.x; acc[2][1] += a2*bv.y; acc[2][2] += a2*bv.z; acc[2][3] += a2*bv.w;
            acc[3][0] += a3*bv.x; acc[3][1] += a3*bv.y; acc[3][2] += a3*bv.z; acc[3][3] += a3*bv.w;
        }
        __syncthreads();
    }

    #pragma unroll
    for (int c = 0; c < 4; c++) {
        int n = n0 + tx*4 + c;
        if (n < 258) {
            float bb = sp_bias(n, mod_b, wdl_b, wep_b, wnc_b, mb_b, wnd_b, wne_b);
            #pragma unroll
            for (int i = 0; i < 4; i++)
                g_small[(m0 + ty*4 + i)*264 + n] = acc[i][c] + bb;
        }
    }
}

// =====================================================================
// Kernel 2: per-batch. Everything is linear in match (match>0 => relu
// factors), so the whole scan reduces to mini-GEMMs over p plus a
// sigmoid epilogue:
//   out[f][r] = sum_p vep0'[p][f]*M0[p][r] + sum_p vep2'[p][f]*M2[p][r]
//             + sum_i w1[i][r]*sym[i][f]
//   M0[p][r]=sum_i match[i][p]*w[3i][r],  M2 likewise with w[3i+2]
//   sym[i][f]=form[f][i] + sig(s1-wnc[f])*(s2-form[f][i]),
//   s1=match@U1, s2=match@U2,  U1=mod0*wch, U2=relu(U1)*vch
// =====================================================================
__global__ __launch_bounds__(256) void scan_kernel(
    const float* __restrict__ form, float* __restrict__ out)
{
    const int b    = blockIdx.x;
    const int tid  = threadIdx.x;
    const int lane = tid & 31, wid = tid >> 5;

    __shared__ float form_s[64][33];                  // [f][r]; later aliased by M0/M2
    __shared__ __align__(16) float big[3072];         // Wk -> U1|U2 -> vep0'|vep2'
    __shared__ float match_s[32][16];
    __shared__ float cw_s[96*32];
    __shared__ float segp_s[256];
    __shared__ __align__(16) float sym_s[32][64];
    __shared__ float sm_s[264];
    __shared__ float wnc_s[64];
    __shared__ float mod0_s[16], wdl_s[16], wep0_s[16], wep2_s[16];
    __shared__ float g_s[96], posn_s[96];
    __shared__ float scal2[2];

    for (int i = tid; i < 2048; i += 256) form_s[i >> 5][i & 31] = form[b*2048 + i];
    for (int j = tid; j < 258; j += 256) sm_s[j] = g_small[b*264 + j];
    for (int i = tid; i < 3072; i += 256)
        big[i] = g_Wk[(i >> 10)*(NB*1024) + b*1024 + (i & 1023)];
    __syncthreads();

    // ---- fold small projections ----
    if (tid < 16) {
        float m[6], mx = -1e30f;
        #pragma unroll
        for (int ch = 0; ch < 6; ch++) { m[ch] = sm_s[tid*6+ch]; mx = fmaxf(mx, m[ch]); }
        float s = 0.f;
        #pragma unroll
        for (int ch = 0; ch < 6; ch++) { m[ch] = __expf(m[ch]-mx); s += m[ch]; }
        float inv = 1.f/s;
        mod0_s[tid] = m[0]*inv;
        wdl_s[tid]  = m[1]*inv*sm_s[96+tid];
        wep0_s[tid] = m[2]*inv*sm_s[112+tid];
        wep2_s[tid] = m[4]*inv*sm_s[128+tid];
    } else if (tid >= 64 && tid < 128) {
        wnc_s[tid-64] = __expf(sm_s[144 + tid-64]);
    } else if (tid == 128) scal2[0] = __expf(sm_s[256]);
    else if (tid == 129)   scal2[1] = __expf(sm_s[257]);

    // ---- match[r][p] = prod_k sigmoid(bk + Wk . form3) ----
    for (int pr = tid; pr < 512; pr += 256) {
        int p = pr >> 5, r = pr & 31;
        float prod = 1.f;
        #pragma unroll
        for (int k = 0; k < 3; k++) {
            float sc = sm_s[208 + k*16 + p];
            int rr = r + k - 1;
            if (rr >= 0 && rr < 32) {
                const float* wkp = &big[k*1024 + p*64];
                #pragma unroll
                for (int f = 0; f < 64; f += 4) {
                    float4 w4 = *(const float4*)&wkp[f];
                    sc += w4.x*form_s[f  ][rr] + w4.y*form_s[f+1][rr]
                        + w4.z*form_s[f+2][rr] + w4.w*form_s[f+3][rr];
                }
            }
            prod *= sigmoidf_(sc);
        }
        match_s[r][p] = prod;
    }
    __syncthreads();

    // ---- U tables (overwrite Wk region) + all 96 gates ----
    {
        const float* pwch = g_wch + b*1024;
        const float* pvch = g_vch + b*1024;
        for (int i = tid; i < 1024; i += 256) {
            float u1 = mod0_s[i >> 6]*pwch[i];
            big[i]        = u1;
            big[1024 + i] = fmaxf(u1, 0.f)*pvch[i];
        }
    }
    if (tid < 96) {
        int i = tid/3, ph = tid - 3*i;
        const float* wv = (ph == 0) ? wep0_s : (ph == 1 ? wdl_s : wep2_s);
        float s = 0.f;
        #pragma unroll
        for (int p = 0; p < 16; p++) s += match_s[i][p]*wv[p];
        g_s[tid] = (ph == 1) ? (1.f - sigmoidf_(s - scal2[0]))
                             : sigmoidf_(s - scal2[1]);
    }
    __syncthreads();

    // ---- exclusive prefix of gates -> posn (warp 0) ----
    if (wid == 0) {
        float a0 = g_s[lane*3+0], a1 = g_s[lane*3+1], a2 = g_s[lane*3+2];
        float loc = a0 + a1 + a2;
        float sc = loc;
        #pragma unroll
        for (int off = 1; off < 32; off <<= 1) {
            float v = __shfl_up_sync(0xffffffffu, sc, off);
            if (lane >= off) sc += v;
        }
        float excl = sc - loc;
        posn_s[lane*3+0] = excl;
        posn_s[lane*3+1] = excl + a0;
        posn_s[lane*3+2] = excl + a0 + a1;
    }
    __syncthreads();

    // ---- c_t[r] = g_t * softmax_r(-2(posn_t-r)^2) ----
    #pragma unroll
    for (int k2 = 0; k2 < 12; k2++) {
        int st = wid*12 + k2;
        float pp = posn_s[st];
        float d  = pp - (float)lane;
        float rstar = fminf(fmaxf(rintf(pp), 0.f), 31.f);
        float dm = pp - rstar;
        float mx = -2.f*dm*dm;
        float e  = __expf(-2.f*d*d - mx);
        float ssum = e;
        #pragma unroll
        for (int off = 16; off; off >>= 1) ssum += __shfl_xor_sync(0xffffffffu, ssum, off);
        cw_s[st*32 + lane] = g_s[st]*e/ssum;
    }
    __syncthreads();

    // ---- suffix products: w_t = c_t * prod_{s>t}(1-c_s) ----
    {
        int st0 = wid*12;
        float run = 1.f;
        #pragma unroll
        for (int k2 = 11; k2 >= 0; k2--) {
            float cc = cw_s[(st0+k2)*32 + lane];
            cw_s[(st0+k2)*32 + lane] = cc*run;
            run *= (1.f - cc);
        }
        segp_s[wid*32 + lane] = run;
    }
    __syncthreads();
    {
        float mult = 1.f;
        #pragma unroll
        for (int w2 = 7; w2 >= 1; w2--) {
            float sp = segp_s[w2*32 + lane];
            if (w2 > wid) mult *= sp;
        }
        if (mult != 1.f) {
            int st0 = wid*12;
            #pragma unroll
            for (int k2 = 0; k2 < 12; k2++)
                cw_s[(st0+k2)*32 + lane] *= mult;
        }
    }
    __syncthreads();

    // ---- sym[i][f]: s1 = match@U1, s2 = match@U2, sigmoid epilogue ----
    {
        int f4 = tid & 15, ii = tid >> 4;
        int f = f4*4;
        #pragma unroll
        for (int rep = 0; rep < 2; rep++) {
            int i = ii + rep*16;
            float4 s1 = {0,0,0,0}, s2 = {0,0,0,0};
            #pragma unroll
            for (int p = 0; p < 16; p++) {
                float m = match_s[i][p];
                float4 u1 = *(const float4*)&big[p*64 + f];
                float4 u2 = *(const float4*)&big[1024 + p*64 + f];
                s1.x += m*u1.x; s1.y += m*u1.y; s1.z += m*u1.z; s1.w += m*u1.w;
                s2.x += m*u2.x; s2.y += m*u2.y; s2.z += m*u2.z; s2.w += m*u2.w;
            }
            float sy0 = form_s[f  ][i], sy1 = form_s[f+1][i];
            float sy2 = form_s[f+2][i], sy3 = form_s[f+3][i];
            float4 v;
            v.x = sy0 + sigmoidf_(s1.x - wnc_s[f  ])*(s2.x - sy0);
            v.y = sy1 + sigmoidf_(s1.y - wnc_s[f+1])*(s2.y - sy1);
            v.z = sy2 + sigmoidf_(s1.z - wnc_s[f+2])*(s2.z - sy2);
            v.w = sy3 + sigmoidf_(s1.w - wnc_s[f+3])*(s2.w - sy3);
            *(float4*)&sym_s[i][f] = v;
        }
    }
    __syncthreads();

    // ---- vep' tables (overwrite U) + M0/M2 (alias dead form_s) ----
    float* M0 = &form_s[0][0];
    float* M2 = M0 + 512;
    {
        const float* pv0 = g_vep0 + b*1024;
        const float* pv2 = g_vep2 + b*1024;
        for (int i = tid; i < 1024; i += 256) {
            int p = i >> 6;
            big[i]        = fmaxf(wep0_s[p], 0.f)*pv0[i];
            big[1024 + i] = fmaxf(wep2_s[p], 0.f)*pv2[i];
        }
    }
    {
        int p0 = wid, p1 = wid + 8;
        float a00 = 0.f, a01 = 0.f, a20 = 0.f, a21 = 0.f;
        #pragma unroll
        for (int i = 0; i < 32; i++) {
            float w0 = cw_s[(3*i  )*32 + lane];
            float w2 = cw_s[(3*i+2)*32 + lane];
            float m0 = match_s[i][p0], m1v = match_s[i][p1];
            a00 += m0*w0;  a01 += m1v*w0;
            a20 += m0*w2;  a21 += m1v*w2;
        }
        M0[p0*32 + lane] = a00; M0[p1*32 + lane] = a01;
        M2[p0*32 + lane] = a20; M2[p1*32 + lane] = a21;
    }
    __syncthreads();

    // ---- out[f][r] ----
    float o[8];
    #pragma unroll
    for (int j = 0; j < 8; j++) o[j] = 0.f;
    const int fb = wid*8;

    #pragma unroll
    for (int p = 0; p < 16; p++) {
        float a0 = M0[p*32 + lane];
        float a2 = M2[p*32 + lane];
        float4 v00 = *(const float4*)&big[p*64 + fb];
        float4 v01 = *(const float4*)&big[p*64 + fb + 4];
        float4 v20 = *(const float4*)&big[1024 + p*64 + fb];
        float4 v21 = *(const float4*)&big[1024 + p*64 + fb + 4];
        o[0] += a0*v00.x + a2*v20.x;  o[1] += a0*v00.y + a2*v20.y;
        o[2] += a0*v00.z + a2*v20.z;  o[3] += a0*v00.w + a2*v20.w;
        o[4] += a0*v01.x + a2*v21.x;  o[5] += a0*v01.y + a2*v21.y;
        o[6] += a0*v01.z + a2*v21.z;  o[7] += a0*v01.w + a2*v21.w;
    }
    #pragma unroll
    for (int i = 0; i < 32; i++) {
        float w1 = cw_s[(3*i+1)*32 + lane];
        float4 s0 = *(const float4*)&sym_s[i][fb];
        float4 s1v = *(const float4*)&sym_s[i][fb + 4];
        o[0] += w1*s0.x;  o[1] += w1*s0.y;  o[2] += w1*s0.z;  o[3] += w1*s0.w;
        o[4] += w1*s1v.x; o[5] += w1*s1v.y; o[6] += w1*s1v.z; o[7] += w1*s1v.w;
    }

    #pragma unroll
    for (int j = 0; j < 8; j++)
        out[b*2048 + (fb + j)*32 + lane] = o[j];
}

// =====================================================================
extern "C" void kernel_launch(void* const* d_in, const int* in_sizes, int n_in,
                              void* d_out, int out_size)
{
    (void)in_sizes; (void)n_in; (void)out_size;
    const float* form  = (const float*)d_in[0];
    const float* ctx   = (const float*)d_in[1];
    const float* mod_W = (const float*)d_in[2];
    const float* mod_b = (const float*)d_in[3];
    const float* wch_W = (const float*)d_in[4];
    const float* wch_b = (const float*)d_in[5];
    const float* wdl_W = (const float*)d_in[6];
    const float* wdl_b = (const float*)d_in[7];
    const float* wep_W = (const float*)d_in[8];
    const float* wep_b = (const float*)d_in[9];
    const float* vch_W = (const float*)d_in[10];
    const float* vch_b = (const float*)d_in[11];
    const float* vep_W = (const float*)d_in[12];
    const float* vep_b = (const float*)d_in[13];
    const float* wnc_W = (const float*)d_in[14];
    const float* wnc_b = (const float*)d_in[15];
    const float* wnd_W = (const float*)d_in[16];
    const float* wnd_b = (const float*)d_in[17];
    const float* wne_W = (const float*)d_in[18];
    const float* wne_b = (const float*)d_in[19];
    const float* m_W   = (const float*)d_in[20];
    const float* m_Wb  = (const float*)d_in[21];
    const float* mb_W  = (const float*)d_in[22];
    const float* mb_b  = (const float*)d_in[23];

    dim3 ggrid(1024/64, NB/64, 7);
    proj_gemm<<<ggrid, 256>>>(ctx, wch_W, wch_b, vch_W, vch_b, vep_W, vep_b, m_W, m_Wb);

    dim3 sgrid(5, NB/64);
    small_proj<<<sgrid, 256>>>(ctx, mod_W, mod_b, wdl_W, wdl_b, wep_W, wep_b,
                               wnc_W, wnc_b, mb_W, mb_b, wnd_W, wnd_b, wne_W, wne_b);

    scan_kernel<<<NB, 256>>>(form, (float*)d_out);
}